// round 13
// baseline (speedup 1.0000x reference)
#include <cuda_runtime.h>
#include <math.h>

typedef unsigned long long ull;

#define BATCH 256
#define SEQT  512
#define EMBD  300
#define HID   150
#define G4    600   // 4*HID
#define HS    152   // padded h stride (16B-aligned)
#define NW2   46    // W smem pair-rows per thread (2 rows x 23 pairs)
#define TSTR  608   // SoA tid stride

#define FMA2(d, a, b) asm("fma.rn.f32x2 %0, %1, %2, %3;" : "=l"(d) : "l"(a), "l"(b), "l"(d))

__device__ __forceinline__ float sig_f(float x)  { return __fdividef(1.f, 1.f + __expf(-x)); }
__device__ __forceinline__ float tanh_f(float x) { return 1.f - __fdividef(2.f, __expf(2.f * x) + 1.f); }

// ---------------- scratch (static device globals; no allocation) ----------------
__device__ float g_e [(size_t)BATCH*SEQT*EMBD];
__device__ float g_xp[(size_t)BATCH*SEQT*G4];
__device__ float g_sa[(size_t)BATCH*SEQT*HID];
__device__ float g_sb[(size_t)BATCH*SEQT*HID];
__device__ float g_hn[BATCH*HID];

// ---------------- profiling-alignment dummy (keeps ncu -s 5 window on lstm_k) ----------------
__global__ void align_k() {
    if (threadIdx.x < HID) g_hn[threadIdx.x] = 0.f;   // overwritten by lstm_k later
}

// ---------------- embedding gather (x is int32 on device) ----------------
__global__ void embed_k(const int* __restrict__ x, const float* __restrict__ emb) {
    int idx = blockIdx.x * blockDim.x + threadIdx.x;
    const int total = BATCH * SEQT * (EMBD / 4);
    if (idx >= total) return;
    int bt = idx / (EMBD / 4);
    int d4 = (idx - bt * (EMBD / 4)) * 4;
    int row = x[bt];
    const float4 v = *(const float4*)(emb + (size_t)row * EMBD + d4);
    *(float4*)(g_e + (size_t)bt * EMBD + d4) = v;
}

// ---------------- x-projection GEMM (round-5 version: best measured) ----------------
__global__ void __launch_bounds__(256) gemm_xproj(
    const float* __restrict__ A, int K,
    const float* __restrict__ W,
    const float* __restrict__ b1,
    const float* __restrict__ b2,
    float* __restrict__ C) {
    __shared__ float As[16][132];
    __shared__ float Bs[16][132];
    const int tid = threadIdx.x;
    const int m0 = blockIdx.x * 128, n0 = blockIdx.y * 128;
    const int tx = tid & 15, ty = tid >> 4;
    const int lr = tid >> 1, lk = (tid & 1) * 8;

    ull acc2[8][4];
#pragma unroll
    for (int i = 0; i < 8; i++)
#pragma unroll
        for (int j = 0; j < 4; j++) acc2[i][j] = 0ull;

    const float* Ap = A + (size_t)(m0 + lr) * K;
    const int nrow = n0 + lr;
    const float* Wp = W + (size_t)nrow * K;
    const bool wok = nrow < G4;
    const int nt = (K + 15) / 16;

    for (int kt = 0; kt < nt; kt++) {
        const int k0 = kt * 16;
#pragma unroll
        for (int c = 0; c < 4; c++) {
            int k = k0 + lk + 2 * c;
            float2 av = (k < K) ? *(const float2*)(Ap + k) : make_float2(0.f, 0.f);
            float2 wv = (wok && k < K) ? *(const float2*)(Wp + k) : make_float2(0.f, 0.f);
            As[lk + 2 * c][lr]     = av.x;
            As[lk + 2 * c + 1][lr] = av.y;
            Bs[lk + 2 * c][lr]     = wv.x;
            Bs[lk + 2 * c + 1][lr] = wv.y;
        }
        __syncthreads();
#pragma unroll
        for (int kk = 0; kk < 16; kk++) {
            float4 al = *(const float4*)&As[kk][ty * 4];
            float4 ah = *(const float4*)&As[kk][64 + ty * 4];
            ulonglong2 bl = *(const ulonglong2*)&Bs[kk][tx * 4];
            ulonglong2 bh = *(const ulonglong2*)&Bs[kk][64 + tx * 4];
            float a_s[8] = {al.x, al.y, al.z, al.w, ah.x, ah.y, ah.z, ah.w};
#pragma unroll
            for (int i = 0; i < 8; i++) {
                float2 t = make_float2(a_s[i], a_s[i]);
                ull ad = *(ull*)&t;
                FMA2(acc2[i][0], ad, bl.x);
                FMA2(acc2[i][1], ad, bl.y);
                FMA2(acc2[i][2], ad, bh.x);
                FMA2(acc2[i][3], ad, bh.y);
            }
        }
        __syncthreads();
    }
#pragma unroll
    for (int i = 0; i < 8; i++) {
        int m = m0 + ((i < 4) ? ty * 4 + i : 64 + ty * 4 + (i - 4));
        float* Cr = C + (size_t)m * G4;
#pragma unroll
        for (int j2 = 0; j2 < 4; j2++) {
            float2 p = *(float2*)&acc2[i][j2];
            int nn = n0 + ((j2 < 2) ? tx * 4 + 2 * j2 : 64 + tx * 4 + 2 * (j2 - 2));
            if (nn < G4)     Cr[nn]     = p.x + b1[nn]     + b2[nn];
            if (nn + 1 < G4) Cr[nn + 1] = p.y + b1[nn + 1] + b2[nn + 1];
        }
    }
}

// ---------------- LSTM layer: ONE CTA per 2 batches, 608 threads, k-split lane quads ----------------
// tid = 4j+2q+s: j = hidden unit, q = gate pair (0: i&g, 1: f&o), s = k-half (parity-interleaved
// 16B chunks). W smem cols [0,92) stored SoA (W2[p][tid], 2wf coalesced reads); cols [92,150)
// in 14 u64 + 1 f32 regs per row. k-halves merge via shfl.xor(1); i*g -> f&o lane via shfl.xor(2).
__global__ void __launch_bounds__(608, 1) lstm_k(
    const float* __restrict__ xp, const float* __restrict__ Whh,
    const int* __restrict__ lengths,
    float* __restrict__ seq_out, float* __restrict__ hn_out, int write_seq)
{
    extern __shared__ float sm[];
    ull*   W2   = (ull*)sm;                 // NW2 x TSTR ull (223744 B)
    float* hbuf = sm + NW2 * TSTR * 2;      // 2 buffers x 2 batches x HS

    const int tid = threadIdx.x;
    const int b0  = blockIdx.x * 2;
    const int j   = tid >> 2;
    const int q   = (tid >> 1) & 1;
    const int s   = tid & 1;
    const bool on = (tid < 600);
    const int jc  = on ? j : 0;
    const int row0 = q * 150 + jc;          // i (q=0) or f (q=1)
    const int row1 = row0 + 300;            // g or o

    // init: each thread fills its own SoA column (46 pairs = 2 rows x 23 pairs)
    for (int p = 0; p < NW2; p++) {
        int pr  = (p < 23) ? p : p - 23;
        int row = (p < 23) ? row0 : row1;
        int col = (pr < 22) ? (8 * (pr >> 1) + 4 * s + 2 * (pr & 1)) : (88 + 2 * s);
        W2[p * TSTR + tid] = *(const ull*)(Whh + (size_t)row * 150 + col);
    }
    for (int idx = tid; idx < 4 * HS; idx += 608) hbuf[idx] = 0.f;

    // register W: cols 92..147 parity chunks (14 u64 per row) + tail col 148+s
    ull w0r[14], w1r[14];
    float w0t, w1t;
    {
        const int cb = 96 - 4 * s;   // s=0 -> chunks 24,26,..; s=1 -> 23,25,..
#pragma unroll
        for (int r = 0; r < 14; r++) {
            int col = cb + 8 * (r >> 1) + 2 * (r & 1);
            w0r[r] = *(const ull*)(Whh + (size_t)row0 * 150 + col);
            w1r[r] = *(const ull*)(Whh + (size_t)row1 * 150 + col);
        }
        w0t = Whh[(size_t)row0 * 150 + 148 + s];
        w1t = Whh[(size_t)row1 * 150 + 148 + s];
    }

    const float* xAb = xp + (size_t)b0 * SEQT * G4;
    const float* xBb = xAb + (size_t)SEQT * G4;
    const int lenA = lengths[b0], lenB = lengths[b0 + 1];
    float cA = 0.f, cB = 0.f, hoA = 0.f, hoB = 0.f;   // writer-lane private state

    __syncthreads();

    for (int t = 0; t < SEQT; t++) {
        const float* hR = hbuf + (t & 1) * (2 * HS);
        float* hW = hbuf + ((t + 1) & 1) * (2 * HS);

        // x loads issued early (hidden under the dot product)
        float xv00 = 0.f, xv01 = 0.f, xv10 = 0.f, xv11 = 0.f;
        if (s == 0 && on) {
            const size_t o = (size_t)t * G4;
            xv00 = xAb[o + row0]; xv01 = xBb[o + row0];
            xv10 = xAb[o + row1]; xv11 = xBb[o + row1];
        }

        ull a00 = 0ull, a01 = 0ull, a10 = 0ull, a11 = 0ull;   // (row, batch)
        const ull* Wl = W2 + tid;
        const float* hRs = hR + 4 * s;
#pragma unroll
        for (int p = 0; p < 22; p++) {
            const int cb = 8 * (p >> 1) + 2 * (p & 1);
            ull w0 = Wl[p * TSTR];
            ull w1 = Wl[(23 + p) * TSTR];
            ull hA = *(const ull*)(hRs + cb);
            ull hB = *(const ull*)(hRs + HS + cb);
            FMA2(a00, w0, hA); FMA2(a01, w0, hB);
            FMA2(a10, w1, hA); FMA2(a11, w1, hB);
        }
        {   // p = 22: cols 88+2s
            ull w0 = Wl[22 * TSTR];
            ull w1 = Wl[45 * TSTR];
            const float* ht = hR + 88 + 2 * s;
            ull hA = *(const ull*)ht;
            ull hB = *(const ull*)(ht + HS);
            FMA2(a00, w0, hA); FMA2(a01, w0, hB);
            FMA2(a10, w1, hA); FMA2(a11, w1, hB);
        }
        {   // register cols 92..147 (parity chunks)
            const float* hq = hR + (96 - 4 * s);
#pragma unroll
            for (int r = 0; r < 14; r++) {
                const int d = 8 * (r >> 1) + 2 * (r & 1);
                ull hA = *(const ull*)(hq + d);
                ull hB = *(const ull*)(hq + HS + d);
                FMA2(a00, w0r[r], hA); FMA2(a01, w0r[r], hB);
                FMA2(a10, w1r[r], hA); FMA2(a11, w1r[r], hB);
            }
        }
        // tail col 148+s (scalar)
        float htA = hR[148 + s], htB = hR[HS + 148 + s];
        float2 f00 = *(float2*)&a00, f01 = *(float2*)&a01;
        float2 f10 = *(float2*)&a10, f11 = *(float2*)&a11;
        float d00 = f00.x + f00.y + w0t * htA + xv00;
        float d01 = f01.x + f01.y + w0t * htB + xv01;
        float d10 = f10.x + f10.y + w1t * htA + xv10;
        float d11 = f11.x + f11.y + w1t * htB + xv11;

        // merge k-halves (both lanes end with the full pre-activation)
        d00 += __shfl_xor_sync(0xffffffffu, d00, 1);
        d01 += __shfl_xor_sync(0xffffffffu, d01, 1);
        d10 += __shfl_xor_sync(0xffffffffu, d10, 1);
        d11 += __shfl_xor_sync(0xffffffffu, d11, 1);

        float v0A = sig_f(d00), v0B = sig_f(d01);                       // i or f
        float v1A = (q == 0) ? tanh_f(d10) : sig_f(d10);                // g or o
        float v1B = (q == 0) ? tanh_f(d11) : sig_f(d11);

        float pA = __shfl_xor_sync(0xffffffffu, v0A * v1A, 2);          // i*g -> q=1 lanes
        float pB = __shfl_xor_sync(0xffffffffu, v0B * v1B, 2);

        if (on && q == 1 && s == 0) {
            float cnA = fmaf(v0A, cA, pA);      // f*c + i*g
            float cnB = fmaf(v0B, cB, pB);
            float hvA = v1A * tanh_f(cnA);      // o * tanh(c)
            float hvB = v1B * tanh_f(cnB);
            bool mA = t < lenA, mB = t < lenB;
            if (write_seq) {
                seq_out[((size_t)b0 * SEQT + t) * HID + j]       = mA ? hvA : 0.f;
                seq_out[((size_t)(b0 + 1) * SEQT + t) * HID + j] = mB ? hvB : 0.f;
            }
            if (mA) { cA = cnA; hoA = hvA; }
            if (mB) { cB = cnB; hoB = hvB; }
            hW[j]      = hoA;
            hW[HS + j] = hoB;
        }
        __syncthreads();
    }

    if (on && q == 1 && s == 0) {
        hn_out[b0 * HID + j]       = hoA;
        hn_out[(b0 + 1) * HID + j] = hoB;
    }
}

// ---------------- FC head ----------------
__global__ void fc_k(const float* __restrict__ hn, const float* __restrict__ w1,
                     const float* __restrict__ b1v, const float* __restrict__ w2,
                     const float* __restrict__ b2v, float* __restrict__ out) {
    __shared__ float red[256];
    int b = blockIdx.x, tid = threadIdx.x;
    float part = 0.f;
    if (tid < HID) {
        float acc = 0.f;
        const float* hr = hn + b * HID;
        const float* wrw = w1 + tid * HID;
        for (int k = 0; k < HID; k++) acc = fmaf(wrw[k], hr[k], acc);
        float z = fmaxf(acc + b1v[tid], 0.f);
        part = z * w2[tid];
    }
    red[tid] = part;
    __syncthreads();
    for (int s = 128; s > 0; s >>= 1) {
        if (tid < s) red[tid] += red[tid + s];
        __syncthreads();
    }
    if (tid == 0) out[b] = red[0] + b2v[0];
}

// ---------------- launch ----------------
extern "C" void kernel_launch(void* const* d_in, const int* in_sizes, int n_in,
                              void* d_out, int out_size) {
    const int* x   = (const int*)d_in[0];
    const int* len = (const int*)d_in[1];
    const float* emb = (const float*)d_in[2];
    const float *Wih[4], *Whh[4], *bih[4], *bhh[4];
    for (int l = 0; l < 4; l++) {
        Wih[l] = (const float*)d_in[3 + 4 * l];
        Whh[l] = (const float*)d_in[4 + 4 * l];
        bih[l] = (const float*)d_in[5 + 4 * l];
        bhh[l] = (const float*)d_in[6 + 4 * l];
    }
    const float* fc1w = (const float*)d_in[19];
    const float* fc1b = (const float*)d_in[20];
    const float* fc2w = (const float*)d_in[21];
    const float* fc2b = (const float*)d_in[22];
    float* out = (float*)d_out;

    float *pe, *pxp, *psa, *psb, *phn;
    cudaGetSymbolAddress((void**)&pe,  g_e);
    cudaGetSymbolAddress((void**)&pxp, g_xp);
    cudaGetSymbolAddress((void**)&psa, g_sa);
    cudaGetSymbolAddress((void**)&psb, g_sb);
    cudaGetSymbolAddress((void**)&phn, g_hn);

    const int SMEM = NW2 * TSTR * 8 + 4 * HS * 4;  // 223744 + 2432 = 226176 B
    cudaFuncSetAttribute(lstm_k, cudaFuncAttributeMaxDynamicSharedMemorySize, SMEM);

    // launch order matters for ncu (-s 5 -c 1): index 5 must be lstm_k (steady state K=150)
    align_k<<<1, 128>>>();                                      // idx 0
    embed_k<<<38400, 256>>>(x, emb);                            // idx 1

    dim3 gg(1024, 5);
    gemm_xproj<<<gg, 256>>>(pe,  EMBD, Wih[0], bih[0], bhh[0], pxp);   // idx 2
    lstm_k<<<128, 608, SMEM>>>(pxp, Whh[0], len, psa, phn, 1);         // idx 3

    gemm_xproj<<<gg, 256>>>(psa, HID,  Wih[1], bih[1], bhh[1], pxp);   // idx 4
    lstm_k<<<128, 608, SMEM>>>(pxp, Whh[1], len, psb, phn, 1);         // idx 5  <- profiled

    gemm_xproj<<<gg, 256>>>(psb, HID,  Wih[2], bih[2], bhh[2], pxp);
    lstm_k<<<128, 608, SMEM>>>(pxp, Whh[2], len, psa, phn, 1);

    gemm_xproj<<<gg, 256>>>(psa, HID,  Wih[3], bih[3], bhh[3], pxp);
    lstm_k<<<128, 608, SMEM>>>(pxp, Whh[3], len, psb, phn, 0);         // hn only

    fc_k<<<256, 256>>>(phn, fc1w, fc1b, fc2w, fc2b, out);
}

// round 14
// speedup vs baseline: 1.0551x; 1.0551x over previous
#include <cuda_runtime.h>
#include <math.h>

typedef unsigned long long ull;

#define BATCH 256
#define SEQT  512
#define EMBD  300
#define HID   150
#define G4    600   // 4*HID
#define HS    152   // padded h stride (16B-aligned)
#define NW2   46    // W smem pair-rows per thread (2 rows x 23 pairs)
#define TSTR  608   // SoA tid stride

#define FMA2(d, a, b) asm("fma.rn.f32x2 %0, %1, %2, %3;" : "=l"(d) : "l"(a), "l"(b), "l"(d))

__device__ __forceinline__ float sig_f(float x)  { return __fdividef(1.f, 1.f + __expf(-x)); }
__device__ __forceinline__ float tanh_f(float x) { return 1.f - __fdividef(2.f, __expf(2.f * x) + 1.f); }

// ---------------- scratch (static device globals; no allocation) ----------------
__device__ float g_e [(size_t)BATCH*SEQT*EMBD];
__device__ float g_xp[(size_t)BATCH*SEQT*G4];
__device__ float g_sa[(size_t)BATCH*SEQT*HID];
__device__ float g_sb[(size_t)BATCH*SEQT*HID];
__device__ float g_hn[BATCH*HID];

// ---------------- profiling-alignment dummy (keeps ncu -s 5 window on lstm_k) ----------------
__global__ void align_k() {
    if (threadIdx.x < HID) g_hn[threadIdx.x] = 0.f;   // overwritten by lstm_k later
}

// ---------------- embedding gather (x is int32 on device) ----------------
__global__ void embed_k(const int* __restrict__ x, const float* __restrict__ emb) {
    int idx = blockIdx.x * blockDim.x + threadIdx.x;
    const int total = BATCH * SEQT * (EMBD / 4);
    if (idx >= total) return;
    int bt = idx / (EMBD / 4);
    int d4 = (idx - bt * (EMBD / 4)) * 4;
    int row = x[bt];
    const float4 v = *(const float4*)(emb + (size_t)row * EMBD + d4);
    *(float4*)(g_e + (size_t)bt * EMBD + d4) = v;
}

// ---------------- x-projection GEMM (round-5 version: best measured) ----------------
__global__ void __launch_bounds__(256) gemm_xproj(
    const float* __restrict__ A, int K,
    const float* __restrict__ W,
    const float* __restrict__ b1,
    const float* __restrict__ b2,
    float* __restrict__ C) {
    __shared__ float As[16][132];
    __shared__ float Bs[16][132];
    const int tid = threadIdx.x;
    const int m0 = blockIdx.x * 128, n0 = blockIdx.y * 128;
    const int tx = tid & 15, ty = tid >> 4;
    const int lr = tid >> 1, lk = (tid & 1) * 8;

    ull acc2[8][4];
#pragma unroll
    for (int i = 0; i < 8; i++)
#pragma unroll
        for (int j = 0; j < 4; j++) acc2[i][j] = 0ull;

    const float* Ap = A + (size_t)(m0 + lr) * K;
    const int nrow = n0 + lr;
    const float* Wp = W + (size_t)nrow * K;
    const bool wok = nrow < G4;
    const int nt = (K + 15) / 16;

    for (int kt = 0; kt < nt; kt++) {
        const int k0 = kt * 16;
#pragma unroll
        for (int c = 0; c < 4; c++) {
            int k = k0 + lk + 2 * c;
            float2 av = (k < K) ? *(const float2*)(Ap + k) : make_float2(0.f, 0.f);
            float2 wv = (wok && k < K) ? *(const float2*)(Wp + k) : make_float2(0.f, 0.f);
            As[lk + 2 * c][lr]     = av.x;
            As[lk + 2 * c + 1][lr] = av.y;
            Bs[lk + 2 * c][lr]     = wv.x;
            Bs[lk + 2 * c + 1][lr] = wv.y;
        }
        __syncthreads();
#pragma unroll
        for (int kk = 0; kk < 16; kk++) {
            float4 al = *(const float4*)&As[kk][ty * 4];
            float4 ah = *(const float4*)&As[kk][64 + ty * 4];
            ulonglong2 bl = *(const ulonglong2*)&Bs[kk][tx * 4];
            ulonglong2 bh = *(const ulonglong2*)&Bs[kk][64 + tx * 4];
            float a_s[8] = {al.x, al.y, al.z, al.w, ah.x, ah.y, ah.z, ah.w};
#pragma unroll
            for (int i = 0; i < 8; i++) {
                float2 t = make_float2(a_s[i], a_s[i]);
                ull ad = *(ull*)&t;
                FMA2(acc2[i][0], ad, bl.x);
                FMA2(acc2[i][1], ad, bl.y);
                FMA2(acc2[i][2], ad, bh.x);
                FMA2(acc2[i][3], ad, bh.y);
            }
        }
        __syncthreads();
    }
#pragma unroll
    for (int i = 0; i < 8; i++) {
        int m = m0 + ((i < 4) ? ty * 4 + i : 64 + ty * 4 + (i - 4));
        float* Cr = C + (size_t)m * G4;
#pragma unroll
        for (int j2 = 0; j2 < 4; j2++) {
            float2 p = *(float2*)&acc2[i][j2];
            int nn = n0 + ((j2 < 2) ? tx * 4 + 2 * j2 : 64 + tx * 4 + 2 * (j2 - 2));
            if (nn < G4)     Cr[nn]     = p.x + b1[nn]     + b2[nn];
            if (nn + 1 < G4) Cr[nn + 1] = p.y + b1[nn + 1] + b2[nn + 1];
        }
    }
}

// ---------------- LSTM layer: ONE CTA per 2 batches, 608 threads, k-split lane quads ----------------
// tid = 4j+2q+s: j = hidden unit, q = gate pair (0: i&g, 1: f&o), s = k-half (parity-interleaved
// 16B chunks). W smem cols [0,92) stored SoA (W2[p][tid], 2wf coalesced reads); cols [92,150)
// in 14 u64 + 1 f32 regs per row. k-halves merge via shfl.xor(1); i*g -> f&o lane via shfl.xor(2).
__global__ void __launch_bounds__(608, 1) lstm_k(
    const float* __restrict__ xp, const float* __restrict__ Whh,
    const int* __restrict__ lengths,
    float* __restrict__ seq_out, float* __restrict__ hn_out, int write_seq)
{
    extern __shared__ float sm[];
    ull*   W2   = (ull*)sm;                 // NW2 x TSTR ull (223744 B)
    float* hbuf = sm + NW2 * TSTR * 2;      // 2 buffers x 2 batches x HS

    const int tid = threadIdx.x;
    const int b0  = blockIdx.x * 2;
    const int j   = tid >> 2;
    const int q   = (tid >> 1) & 1;
    const int s   = tid & 1;
    const bool on = (tid < 600);
    const int jc  = on ? j : 0;
    const int row0 = q * 150 + jc;          // i (q=0) or f (q=1)
    const int row1 = row0 + 300;            // g or o

    // init: each thread fills its own SoA column (46 pairs = 2 rows x 23 pairs)
    for (int p = 0; p < NW2; p++) {
        int pr  = (p < 23) ? p : p - 23;
        int row = (p < 23) ? row0 : row1;
        int col = (pr < 22) ? (8 * (pr >> 1) + 4 * s + 2 * (pr & 1)) : (88 + 2 * s);
        W2[p * TSTR + tid] = *(const ull*)(Whh + (size_t)row * 150 + col);
    }
    for (int idx = tid; idx < 4 * HS; idx += 608) hbuf[idx] = 0.f;

    // register W: cols 92..147 parity chunks (14 u64 per row) + tail col 148+s
    ull w0r[14], w1r[14];
    float w0t, w1t;
    {
        const int cb = 96 - 4 * s;   // s=0 -> chunks 24,26,..; s=1 -> 23,25,..
#pragma unroll
        for (int r = 0; r < 14; r++) {
            int col = cb + 8 * (r >> 1) + 2 * (r & 1);
            w0r[r] = *(const ull*)(Whh + (size_t)row0 * 150 + col);
            w1r[r] = *(const ull*)(Whh + (size_t)row1 * 150 + col);
        }
        w0t = Whh[(size_t)row0 * 150 + 148 + s];
        w1t = Whh[(size_t)row1 * 150 + 148 + s];
    }

    const float* xAb = xp + (size_t)b0 * SEQT * G4;
    const float* xBb = xAb + (size_t)SEQT * G4;
    const int lenA = lengths[b0], lenB = lengths[b0 + 1];
    float cA = 0.f, cB = 0.f, hoA = 0.f, hoB = 0.f;   // writer-lane private state

    __syncthreads();

    for (int t = 0; t < SEQT; t++) {
        const float* hR = hbuf + (t & 1) * (2 * HS);
        float* hW = hbuf + ((t + 1) & 1) * (2 * HS);

        // x loads issued early (hidden under the dot product)
        float xv00 = 0.f, xv01 = 0.f, xv10 = 0.f, xv11 = 0.f;
        if (s == 0 && on) {
            const size_t o = (size_t)t * G4;
            xv00 = xAb[o + row0]; xv01 = xBb[o + row0];
            xv10 = xAb[o + row1]; xv11 = xBb[o + row1];
        }

        ull a00 = 0ull, a01 = 0ull, a10 = 0ull, a11 = 0ull;   // (row, batch)
        const ull* Wl = W2 + tid;
        const float* hRs = hR + 4 * s;
#pragma unroll
        for (int p = 0; p < 22; p++) {
            const int cb = 8 * (p >> 1) + 2 * (p & 1);
            ull w0 = Wl[p * TSTR];
            ull w1 = Wl[(23 + p) * TSTR];
            ull hA = *(const ull*)(hRs + cb);
            ull hB = *(const ull*)(hRs + HS + cb);
            FMA2(a00, w0, hA); FMA2(a01, w0, hB);
            FMA2(a10, w1, hA); FMA2(a11, w1, hB);
        }
        {   // p = 22: cols 88+2s
            ull w0 = Wl[22 * TSTR];
            ull w1 = Wl[45 * TSTR];
            const float* ht = hR + 88 + 2 * s;
            ull hA = *(const ull*)ht;
            ull hB = *(const ull*)(ht + HS);
            FMA2(a00, w0, hA); FMA2(a01, w0, hB);
            FMA2(a10, w1, hA); FMA2(a11, w1, hB);
        }
        {   // register cols 92..147 (parity chunks)
            const float* hq = hR + (96 - 4 * s);
#pragma unroll
            for (int r = 0; r < 14; r++) {
                const int d = 8 * (r >> 1) + 2 * (r & 1);
                ull hA = *(const ull*)(hq + d);
                ull hB = *(const ull*)(hq + HS + d);
                FMA2(a00, w0r[r], hA); FMA2(a01, w0r[r], hB);
                FMA2(a10, w1r[r], hA); FMA2(a11, w1r[r], hB);
            }
        }
        // tail col 148+s (scalar)
        float htA = hR[148 + s], htB = hR[HS + 148 + s];
        float2 f00 = *(float2*)&a00, f01 = *(float2*)&a01;
        float2 f10 = *(float2*)&a10, f11 = *(float2*)&a11;
        float d00 = f00.x + f00.y + w0t * htA + xv00;
        float d01 = f01.x + f01.y + w0t * htB + xv01;
        float d10 = f10.x + f10.y + w1t * htA + xv10;
        float d11 = f11.x + f11.y + w1t * htB + xv11;

        // merge k-halves (both lanes end with the full pre-activation)
        d00 += __shfl_xor_sync(0xffffffffu, d00, 1);
        d01 += __shfl_xor_sync(0xffffffffu, d01, 1);
        d10 += __shfl_xor_sync(0xffffffffu, d10, 1);
        d11 += __shfl_xor_sync(0xffffffffu, d11, 1);

        float v0A = sig_f(d00), v0B = sig_f(d01);                       // i or f
        float v1A = (q == 0) ? tanh_f(d10) : sig_f(d10);                // g or o
        float v1B = (q == 0) ? tanh_f(d11) : sig_f(d11);

        float pA = __shfl_xor_sync(0xffffffffu, v0A * v1A, 2);          // i*g -> q=1 lanes
        float pB = __shfl_xor_sync(0xffffffffu, v0B * v1B, 2);

        if (on && q == 1 && s == 0) {
            float cnA = fmaf(v0A, cA, pA);      // f*c + i*g
            float cnB = fmaf(v0B, cB, pB);
            float hvA = v1A * tanh_f(cnA);      // o * tanh(c)
            float hvB = v1B * tanh_f(cnB);
            bool mA = t < lenA, mB = t < lenB;
            if (write_seq) {
                seq_out[((size_t)b0 * SEQT + t) * HID + j]       = mA ? hvA : 0.f;
                seq_out[((size_t)(b0 + 1) * SEQT + t) * HID + j] = mB ? hvB : 0.f;
            }
            if (mA) { cA = cnA; hoA = hvA; }
            if (mB) { cB = cnB; hoB = hvB; }
            hW[j]      = hoA;
            hW[HS + j] = hoB;
        }
        __syncthreads();
    }

    if (on && q == 1 && s == 0) {
        hn_out[b0 * HID + j]       = hoA;
        hn_out[(b0 + 1) * HID + j] = hoB;
    }
}

// ---------------- FC head ----------------
__global__ void fc_k(const float* __restrict__ hn, const float* __restrict__ w1,
                     const float* __restrict__ b1v, const float* __restrict__ w2,
                     const float* __restrict__ b2v, float* __restrict__ out) {
    __shared__ float red[256];
    int b = blockIdx.x, tid = threadIdx.x;
    float part = 0.f;
    if (tid < HID) {
        float acc = 0.f;
        const float* hr = hn + b * HID;
        const float* wrw = w1 + tid * HID;
        for (int k = 0; k < HID; k++) acc = fmaf(wrw[k], hr[k], acc);
        float z = fmaxf(acc + b1v[tid], 0.f);
        part = z * w2[tid];
    }
    red[tid] = part;
    __syncthreads();
    for (int s = 128; s > 0; s >>= 1) {
        if (tid < s) red[tid] += red[tid + s];
        __syncthreads();
    }
    if (tid == 0) out[b] = red[0] + b2v[0];
}

// ---------------- launch ----------------
extern "C" void kernel_launch(void* const* d_in, const int* in_sizes, int n_in,
                              void* d_out, int out_size) {
    const int* x   = (const int*)d_in[0];
    const int* len = (const int*)d_in[1];
    const float* emb = (const float*)d_in[2];
    const float *Wih[4], *Whh[4], *bih[4], *bhh[4];
    for (int l = 0; l < 4; l++) {
        Wih[l] = (const float*)d_in[3 + 4 * l];
        Whh[l] = (const float*)d_in[4 + 4 * l];
        bih[l] = (const float*)d_in[5 + 4 * l];
        bhh[l] = (const float*)d_in[6 + 4 * l];
    }
    const float* fc1w = (const float*)d_in[19];
    const float* fc1b = (const float*)d_in[20];
    const float* fc2w = (const float*)d_in[21];
    const float* fc2b = (const float*)d_in[22];
    float* out = (float*)d_out;

    float *pe, *pxp, *psa, *psb, *phn;
    cudaGetSymbolAddress((void**)&pe,  g_e);
    cudaGetSymbolAddress((void**)&pxp, g_xp);
    cudaGetSymbolAddress((void**)&psa, g_sa);
    cudaGetSymbolAddress((void**)&psb, g_sb);
    cudaGetSymbolAddress((void**)&phn, g_hn);

    const int SMEM = NW2 * TSTR * 8 + 4 * HS * 4;  // 223744 + 2432 = 226176 B
    cudaFuncSetAttribute(lstm_k, cudaFuncAttributeMaxDynamicSharedMemorySize, SMEM);

    // launch order matters for ncu (-s 5 -c 1): index 5 must be lstm_k (steady state K=150)
    align_k<<<1, 128>>>();                                      // idx 0
    embed_k<<<38400, 256>>>(x, emb);                            // idx 1

    dim3 gg(1024, 5);
    gemm_xproj<<<gg, 256>>>(pe,  EMBD, Wih[0], bih[0], bhh[0], pxp);   // idx 2
    lstm_k<<<128, 608, SMEM>>>(pxp, Whh[0], len, psa, phn, 1);         // idx 3

    gemm_xproj<<<gg, 256>>>(psa, HID,  Wih[1], bih[1], bhh[1], pxp);   // idx 4
    lstm_k<<<128, 608, SMEM>>>(pxp, Whh[1], len, psb, phn, 1);         // idx 5  <- profiled

    gemm_xproj<<<gg, 256>>>(psb, HID,  Wih[2], bih[2], bhh[2], pxp);
    lstm_k<<<128, 608, SMEM>>>(pxp, Whh[2], len, psa, phn, 1);

    gemm_xproj<<<gg, 256>>>(psa, HID,  Wih[3], bih[3], bhh[3], pxp);
    lstm_k<<<128, 608, SMEM>>>(pxp, Whh[3], len, psb, phn, 0);         // hn only

    fc_k<<<256, 256>>>(phn, fc1w, fc1b, fc2w, fc2b, out);
}

// round 16
// speedup vs baseline: 1.0631x; 1.0075x over previous
#include <cuda_runtime.h>
#include <math.h>

typedef unsigned long long ull;

#define BATCH 256
#define SEQT  512
#define EMBD  300
#define HID   150
#define G4    600   // 4*HID
#define HS    152   // padded h stride (16B-aligned; cols 150,151 stay zero)
#define NSM   23    // W smem slots per thread (16B each)
#define SMW_B (NSM * 608 * 16)        // 223744 B
#define SMEM_TOT (SMW_B + 4 * HS * 4) // + hbuf = 226176 B

#define FMA2(d, a, b) asm("fma.rn.f32x2 %0, %1, %2, %3;" : "=l"(d) : "l"(a), "l"(b), "l"(d))

__device__ __forceinline__ float sig_f(float x)  { return __fdividef(1.f, 1.f + __expf(-x)); }
__device__ __forceinline__ float tanh_f(float x) { return 1.f - __fdividef(2.f, __expf(2.f * x) + 1.f); }

// ---------------- scratch (static device globals; no allocation) ----------------
__device__ float g_e [(size_t)BATCH*SEQT*EMBD];
__device__ float g_xp[(size_t)BATCH*SEQT*G4];
__device__ float g_sa[(size_t)BATCH*SEQT*HID];
__device__ float g_sb[(size_t)BATCH*SEQT*HID];
__device__ float g_hn[BATCH*HID];

// ---------------- profiling-alignment dummy (keeps ncu -s 5 window on lstm_k) ----------------
__global__ void align_k() {
    if (threadIdx.x < HID) g_hn[threadIdx.x] = 0.f;
}

// ---------------- embedding gather (x is int32 on device) ----------------
__global__ void embed_k(const int* __restrict__ x, const float* __restrict__ emb) {
    int idx = blockIdx.x * blockDim.x + threadIdx.x;
    const int total = BATCH * SEQT * (EMBD / 4);
    if (idx >= total) return;
    int bt = idx / (EMBD / 4);
    int d4 = (idx - bt * (EMBD / 4)) * 4;
    int row = x[bt];
    *(float4*)(g_e + (size_t)bt * EMBD + d4) = *(const float4*)(emb + (size_t)row * EMBD + d4);
}

// ---------------- x-projection GEMM (round-5 version: best measured) ----------------
__global__ void __launch_bounds__(256) gemm_xproj(
    const float* __restrict__ A, int K,
    const float* __restrict__ W,
    const float* __restrict__ b1,
    const float* __restrict__ b2,
    float* __restrict__ C) {
    __shared__ float As[16][132];
    __shared__ float Bs[16][132];
    const int tid = threadIdx.x;
    const int m0 = blockIdx.x * 128, n0 = blockIdx.y * 128;
    const int tx = tid & 15, ty = tid >> 4;
    const int lr = tid >> 1, lk = (tid & 1) * 8;

    ull acc2[8][4];
#pragma unroll
    for (int i = 0; i < 8; i++)
#pragma unroll
        for (int j = 0; j < 4; j++) acc2[i][j] = 0ull;

    const float* Ap = A + (size_t)(m0 + lr) * K;
    const int nrow = n0 + lr;
    const float* Wp = W + (size_t)nrow * K;
    const bool wok = nrow < G4;
    const int nt = (K + 15) / 16;

    for (int kt = 0; kt < nt; kt++) {
        const int k0 = kt * 16;
#pragma unroll
        for (int c = 0; c < 4; c++) {
            int k = k0 + lk + 2 * c;
            float2 av = (k < K) ? *(const float2*)(Ap + k) : make_float2(0.f, 0.f);
            float2 wv = (wok && k < K) ? *(const float2*)(Wp + k) : make_float2(0.f, 0.f);
            As[lk + 2 * c][lr]     = av.x;
            As[lk + 2 * c + 1][lr] = av.y;
            Bs[lk + 2 * c][lr]     = wv.x;
            Bs[lk + 2 * c + 1][lr] = wv.y;
        }
        __syncthreads();
#pragma unroll
        for (int kk = 0; kk < 16; kk++) {
            float4 al = *(const float4*)&As[kk][ty * 4];
            float4 ah = *(const float4*)&As[kk][64 + ty * 4];
            ulonglong2 bl = *(const ulonglong2*)&Bs[kk][tx * 4];
            ulonglong2 bh = *(const ulonglong2*)&Bs[kk][64 + tx * 4];
            float a_s[8] = {al.x, al.y, al.z, al.w, ah.x, ah.y, ah.z, ah.w};
#pragma unroll
            for (int i = 0; i < 8; i++) {
                float2 t = make_float2(a_s[i], a_s[i]);
                ull ad = *(ull*)&t;
                FMA2(acc2[i][0], ad, bl.x);
                FMA2(acc2[i][1], ad, bl.y);
                FMA2(acc2[i][2], ad, bh.x);
                FMA2(acc2[i][3], ad, bh.y);
            }
        }
        __syncthreads();
    }
#pragma unroll
    for (int i = 0; i < 8; i++) {
        int m = m0 + ((i < 4) ? ty * 4 + i : 64 + ty * 4 + (i - 4));
        float* Cr = C + (size_t)m * G4;
#pragma unroll
        for (int j2 = 0; j2 < 4; j2++) {
            float2 p = *(float2*)&acc2[i][j2];
            int nn = n0 + ((j2 < 2) ? tx * 4 + 2 * j2 : 64 + tx * 4 + 2 * (j2 - 2));
            if (nn < G4)     Cr[nn]     = p.x + b1[nn]     + b2[nn];
            if (nn + 1 < G4) Cr[nn + 1] = p.y + b1[nn + 1] + b2[nn + 1];
        }
    }
}

// ---------------- LSTM layer: ONE CTA per 2 batches, 608 threads ----------------
// tid = 4j+2q+s: j = hidden unit, q = gate pair (0: i&g, 1: f&o), s = 16B-chunk parity.
// Chunks c = 2n+s, cols 4c..4c+3, n = 0..18 (chunk 37 covers tail cols 148..151, zero-padded).
// W: 23 slots smem (LDS.128, SoA by slot) + 15 float4 in regs per thread.
// k-halves merge via shfl.xor(1); lane s owns batch s activations+state; i*g via shfl.xor(2).
__global__ void __launch_bounds__(608, 1) lstm_k(
    const float* __restrict__ xp, const float* __restrict__ Whh,
    const int* __restrict__ lengths,
    float* __restrict__ seq_out, float* __restrict__ hn_out, int write_seq)
{
    extern __shared__ char smem[];
    float* hbuf = (float*)(smem + SMW_B);   // 2 buffers x 2 batches x HS

    const int tid = threadIdx.x;
    const int b0  = blockIdx.x * 2;
    const int j   = tid >> 2;
    const int q   = (tid >> 1) & 1;
    const int s   = tid & 1;
    const bool on = (tid < 600);
    const int jc  = on ? j : 0;
    const int row0 = q * 150 + jc;          // i (q=0) or f (q=1)
    const int row1 = row0 + 300;            // g or o

    // W smem init: slots 0..11 -> row0 n=0..11; slots 12..22 -> row1 n=0..10
    for (int sl = 0; sl < NSM; sl++) {
        int row = (sl < 12) ? row0 : row1;
        int n   = (sl < 12) ? sl : sl - 12;
        int k0  = 8 * n + 4 * s;
        float4 v;
        v.x = (k0     < 150) ? Whh[(size_t)row * 150 + k0]     : 0.f;
        v.y = (k0 + 1 < 150) ? Whh[(size_t)row * 150 + k0 + 1] : 0.f;
        v.z = (k0 + 2 < 150) ? Whh[(size_t)row * 150 + k0 + 2] : 0.f;
        v.w = (k0 + 3 < 150) ? Whh[(size_t)row * 150 + k0 + 3] : 0.f;
        *(float4*)(smem + ((size_t)sl * 608 + tid) * 16) = v;
    }
    for (int idx = tid; idx < 4 * HS; idx += 608) hbuf[idx] = 0.f;

    // W regs: row0 n=12..18 (7), row1 n=11..18 (8)
    float4 w0r4[7], w1r4[8];
#pragma unroll
    for (int r = 0; r < 7; r++) {
        int k0 = 8 * (12 + r) + 4 * s;
        float4 v;
        v.x = (k0     < 150) ? Whh[(size_t)row0 * 150 + k0]     : 0.f;
        v.y = (k0 + 1 < 150) ? Whh[(size_t)row0 * 150 + k0 + 1] : 0.f;
        v.z = (k0 + 2 < 150) ? Whh[(size_t)row0 * 150 + k0 + 2] : 0.f;
        v.w = (k0 + 3 < 150) ? Whh[(size_t)row0 * 150 + k0 + 3] : 0.f;
        w0r4[r] = v;
    }
#pragma unroll
    for (int r = 0; r < 8; r++) {
        int k0 = 8 * (11 + r) + 4 * s;
        float4 v;
        v.x = (k0     < 150) ? Whh[(size_t)row1 * 150 + k0]     : 0.f;
        v.y = (k0 + 1 < 150) ? Whh[(size_t)row1 * 150 + k0 + 1] : 0.f;
        v.z = (k0 + 2 < 150) ? Whh[(size_t)row1 * 150 + k0 + 2] : 0.f;
        v.w = (k0 + 3 < 150) ? Whh[(size_t)row1 * 150 + k0 + 3] : 0.f;
        w1r4[r] = v;
    }

    const float* xb = xp + (size_t)(b0 + s) * SEQT * G4;   // lane s owns batch b0+s
    const int mylen = lengths[b0 + s];
    float cst = 0.f, hst = 0.f;                            // q=1 lane state (batch s)
    const char* Wme = smem + (size_t)tid * 16;

    __syncthreads();

    for (int t = 0; t < SEQT; t++) {
        const float* hR = hbuf + (t & 1) * (2 * HS);
        float* hW = hbuf + ((t + 1) & 1) * (2 * HS);

        // xg for batch s (early)
        const size_t xo = (size_t)t * G4;
        float xg0 = xb[xo + row0];
        float xg1 = xb[xo + row1];

        ull a00 = 0ull, a01 = 0ull, a10 = 0ull, a11 = 0ull;   // (row, batch)
        const int koff = 4 * s;
#pragma unroll
        for (int n = 0; n < 19; n++) {
            float4 w0 = (n < 12) ? *(const float4*)(Wme + (size_t)n * 9728)
                                 : w0r4[n - 12];
            float4 w1 = (n < 11) ? *(const float4*)(Wme + (size_t)(12 + n) * 9728)
                                 : w1r4[n - 11];
            const int k = 8 * n + koff;
            float4 ha = *(const float4*)(hR + k);
            float4 hb = *(const float4*)(hR + HS + k);
            ulonglong2 W0 = *(ulonglong2*)&w0, W1 = *(ulonglong2*)&w1;
            ulonglong2 HA = *(ulonglong2*)&ha, HB = *(ulonglong2*)&hb;
            FMA2(a00, W0.x, HA.x); FMA2(a00, W0.y, HA.y);
            FMA2(a01, W0.x, HB.x); FMA2(a01, W0.y, HB.y);
            FMA2(a10, W1.x, HA.x); FMA2(a10, W1.y, HA.y);
            FMA2(a11, W1.x, HB.x); FMA2(a11, W1.y, HB.y);
        }
        float2 f00 = *(float2*)&a00, f01 = *(float2*)&a01;
        float2 f10 = *(float2*)&a10, f11 = *(float2*)&a11;
        float r00 = f00.x + f00.y, r01 = f01.x + f01.y;
        float r10 = f10.x + f10.y, r11 = f11.x + f11.y;
        // merge k-halves across s-lanes
        r00 += __shfl_xor_sync(0xffffffffu, r00, 1);
        r01 += __shfl_xor_sync(0xffffffffu, r01, 1);
        r10 += __shfl_xor_sync(0xffffffffu, r10, 1);
        r11 += __shfl_xor_sync(0xffffffffu, r11, 1);

        // lane s handles batch s only
        float pre0 = (s ? r01 : r00) + xg0;   // i (q=0) / f (q=1)
        float pre1 = (s ? r11 : r10) + xg1;   // g (q=0) / o (q=1)

        float v0 = sig_f(pre0);
        // v1: tanh for q=0 (g), sigma via tanh identity for q=1 (o) -> one MUFU path
        float tin = q ? 0.5f * pre1 : pre1;
        float tv  = tanh_f(tin);
        float v1  = q ? fmaf(0.5f, tv, 0.5f) : tv;

        float p = __shfl_xor_sync(0xffffffffu, v0 * v1, 2);   // i*g -> q=1 lane, same s

        if (on && q == 1) {
            float cn = fmaf(v0, cst, p);        // f*c + i*g
            float hv = v1 * tanh_f(cn);         // o * tanh(c)
            bool m = t < mylen;
            if (write_seq)
                seq_out[((size_t)(b0 + s) * SEQT + t) * HID + j] = m ? hv : 0.f;
            if (m) { cst = cn; hst = hv; }
            hW[s * HS + j] = hst;
        }
        __syncthreads();
    }

    if (on && q == 1)
        hn_out[(b0 + s) * HID + j] = hst;
}

// ---------------- FC head ----------------
__global__ void fc_k(const float* __restrict__ hn, const float* __restrict__ w1,
                     const float* __restrict__ b1v, const float* __restrict__ w2,
                     const float* __restrict__ b2v, float* __restrict__ out) {
    __shared__ float red[256];
    int b = blockIdx.x, tid = threadIdx.x;
    float part = 0.f;
    if (tid < HID) {
        float acc = 0.f;
        const float* hr = hn + b * HID;
        const float* wr = w1 + tid * HID;
        for (int k = 0; k < HID; k++) acc = fmaf(wr[k], hr[k], acc);
        part = fmaxf(acc + b1v[tid], 0.f) * w2[tid];
    }
    red[tid] = part;
    __syncthreads();
    for (int st = 128; st > 0; st >>= 1) {
        if (tid < st) red[tid] += red[tid + st];
        __syncthreads();
    }
    if (tid == 0) out[b] = red[0] + b2v[0];
}

// ---------------- launch ----------------
extern "C" void kernel_launch(void* const* d_in, const int* in_sizes, int n_in,
                              void* d_out, int out_size) {
    const int* x   = (const int*)d_in[0];
    const int* len = (const int*)d_in[1];
    const float* emb = (const float*)d_in[2];
    const float *Wih[4], *Whh[4], *bih[4], *bhh[4];
    for (int l = 0; l < 4; l++) {
        Wih[l] = (const float*)d_in[3 + 4 * l];
        Whh[l] = (const float*)d_in[4 + 4 * l];
        bih[l] = (const float*)d_in[5 + 4 * l];
        bhh[l] = (const float*)d_in[6 + 4 * l];
    }
    const float* fc1w = (const float*)d_in[19];
    const float* fc1b = (const float*)d_in[20];
    const float* fc2w = (const float*)d_in[21];
    const float* fc2b = (const float*)d_in[22];
    float* out = (float*)d_out;

    float *pe, *pxp, *psa, *psb, *phn;
    cudaGetSymbolAddress((void**)&pe,  g_e);
    cudaGetSymbolAddress((void**)&pxp, g_xp);
    cudaGetSymbolAddress((void**)&psa, g_sa);
    cudaGetSymbolAddress((void**)&psb, g_sb);
    cudaGetSymbolAddress((void**)&phn, g_hn);

    cudaFuncSetAttribute(lstm_k, cudaFuncAttributeMaxDynamicSharedMemorySize, SMEM_TOT);

    // launch order matters for ncu (-s 5 -c 1): index 5 must be lstm_k (steady state K=150)
    align_k<<<1, 128>>>();                                      // idx 0
    embed_k<<<38400, 256>>>(x, emb);                            // idx 1

    dim3 gg(1024, 5);
    gemm_xproj<<<gg, 256>>>(pe,  EMBD, Wih[0], bih[0], bhh[0], pxp);   // idx 2
    lstm_k<<<128, 608, SMEM_TOT>>>(pxp, Whh[0], len, psa, phn, 1);     // idx 3

    gemm_xproj<<<gg, 256>>>(psa, HID,  Wih[1], bih[1], bhh[1], pxp);   // idx 4
    lstm_k<<<128, 608, SMEM_TOT>>>(pxp, Whh[1], len, psb, phn, 1);     // idx 5  <- profiled

    gemm_xproj<<<gg, 256>>>(psb, HID,  Wih[2], bih[2], bhh[2], pxp);
    lstm_k<<<128, 608, SMEM_TOT>>>(pxp, Whh[2], len, psa, phn, 1);

    gemm_xproj<<<gg, 256>>>(psa, HID,  Wih[3], bih[3], bhh[3], pxp);
    lstm_k<<<128, 608, SMEM_TOT>>>(pxp, Whh[3], len, psb, phn, 0);     // hn only

    fc_k<<<256, 256>>>(phn, fc1w, fc1b, fc2w, fc2b, out);
}